// round 3
// baseline (speedup 1.0000x reference)
#include <cuda_runtime.h>
#include <math.h>

#define LROWS    512
#define NS       8192            // samples per row
#define NREF     8192            // reference grid points
#define NG       (3*NREF)        // 24576 circular-CDF grid points
#define NTHREADS 512
#define IPT      (NS/NTHREADS)   // 16 items per thread
#define KPT      (NREF/NTHREADS) // 16 inversion queries per thread
#define QB       8               // query batch for lockstep bisection

#define STEPG     (3.0f/24575.0f)
#define INV_STEPG (24575.0f/3.0f)

__device__ float g_rowsum[LROWS];
__device__ float g_h[(size_t)2 * LROWS * NS];   // h1 then h2, 32 MB scratch

// ---------------------------------------------------------------------------
// block-wide exclusive scans (warp shuffle + 16-entry partials)
// ---------------------------------------------------------------------------
__device__ __forceinline__ int block_excl_scan_int(int local_total, int tid, int* s_part)
{
    __syncthreads();
    int lane = tid & 31, wid = tid >> 5;
    int x = local_total;
#pragma unroll
    for (int d = 1; d < 32; d <<= 1) {
        int t = __shfl_up_sync(0xffffffffu, x, d);
        if (lane >= d) x += t;
    }
    if (lane == 31) s_part[wid] = x;
    __syncthreads();
    if (wid == 0) {
        int v = (lane < 16) ? s_part[lane] : 0;
        int y = v;
#pragma unroll
        for (int d = 1; d < 16; d <<= 1) {
            int t = __shfl_up_sync(0xffffffffu, y, d);
            if (lane >= d) y += t;
        }
        if (lane < 16) s_part[lane] = y - v;
    }
    __syncthreads();
    return s_part[wid] + (x - local_total);
}

__device__ __forceinline__ float block_excl_scan_float(float local_total, int tid, float* s_part)
{
    __syncthreads();
    int lane = tid & 31, wid = tid >> 5;
    float x = local_total;
#pragma unroll
    for (int d = 1; d < 32; d <<= 1) {
        float t = __shfl_up_sync(0xffffffffu, x, d);
        if (lane >= d) x += t;
    }
    if (lane == 31) s_part[wid] = x;
    __syncthreads();
    if (wid == 0) {
        float v = (lane < 16) ? s_part[lane] : 0.f;
        float y = v;
#pragma unroll
        for (int d = 1; d < 16; d <<= 1) {
            float t = __shfl_up_sync(0xffffffffu, y, d);
            if (lane >= d) y += t;
        }
        if (lane < 16) s_part[lane] = y - v;
    }
    __syncthreads();
    return s_part[wid] + (x - local_total);
}

// smallest j in [jmin, jmax] with r(j,p) > v, where r(j,p)=fmaf(j,STEPG,-1)-(p-1)
__device__ __forceinline__ int find_jstart(float v, int p, int jmin, int jmax)
{
    float fi = (float)(p - 1);
    float est = (v + (float)p) * INV_STEPG;
    int j = (int)est - 3;
    if (j < jmin) j = jmin;
    if (j > jmax) j = jmax;
    while (j > jmin) {
        float r = fmaf((float)(j - 1), STEPG, -1.0f) - fi;
        if (r > v) j--; else break;
    }
    while (j < jmax) {
        float r = fmaf((float)j, STEPG, -1.0f) - fi;
        if (r <= v) j++; else break;
    }
    return j;
}

// ---------------------------------------------------------------------------
// one embedding pass per block: grid = 1024 = 2 datasets x 512 rows
// ---------------------------------------------------------------------------
__global__ void __launch_bounds__(NTHREADS, 1)
lcot_emb_kernel(const float* __restrict__ x1, const float* __restrict__ w1,
                const float* __restrict__ x2, const float* __restrict__ w2)
{
    extern __shared__ char smem_raw[];
    float* xs   = (float*)smem_raw;            // [NS]
    float* cw   = xs + NS;                     // [NS]
    int*   offs = (int*)(cw + NS);             // [NS+1]
    float* ecdf = (float*)(offs + (NS + 1));   // [NG]

    __shared__ float s_pf[16];
    __shared__ float s_pf2[16];
    __shared__ int   s_pi[16];
    __shared__ float s_alpha;

    const int tid = threadIdx.x;
    const int bid = blockIdx.x;
    const int row = bid & (LROWS - 1);
    const int ds  = bid >> 9;
    const size_t base = (size_t)row * NS;
    const float* gx = (ds ? x2 : x1) + base;
    const float* gw = (ds ? w2 : w1) + base;
    float* hout = g_h + (size_t)bid * NS;

    // ---- 1. zero histogram --------------------------------------------------
    for (int i = tid; i <= NS; i += NTHREADS) offs[i] = 0;
    __syncthreads();

    // ---- 2. load, histogram, alpha partials ---------------------------------
    float lx[IPT], lw[IPT];
    float pxw = 0.f, pw = 0.f;
#pragma unroll
    for (int i = 0; i < IPT; i++) {
        int idx = tid + i * NTHREADS;
        float x = gx[idx];
        float w = gw[idx];
        lx[i] = x; lw[i] = w;
        pxw += x * w; pw += w;
        int b = (int)(x * 8192.0f);            // exact order-preserving bucket
        if (b > NS - 1) b = NS - 1;
        atomicAdd(&offs[b + 1], 1);
    }
    {
        int lane = tid & 31, wid = tid >> 5;
        float a = pxw, b = pw;
#pragma unroll
        for (int d = 16; d > 0; d >>= 1) {
            a += __shfl_down_sync(0xffffffffu, a, d);
            b += __shfl_down_sync(0xffffffffu, b, d);
        }
        if (lane == 0) { s_pf[wid] = a; s_pf2[wid] = b; }
        __syncthreads();                       // also fences histogram atomics
        if (tid == 0) {
            float sa = 0.f, sb = 0.f;
#pragma unroll
            for (int k = 0; k < 16; k++) { sa += s_pf[k]; sb += s_pf2[k]; }
            s_alpha = sa / sb - 0.5f;
        }
    }

    // ---- 3. exclusive scan of counts -> bucket offsets ----------------------
    {
        int c[IPT]; int runc = 0;
#pragma unroll
        for (int j = 0; j < IPT; j++) {
            runc += offs[1 + tid * IPT + j];
            c[j] = runc;
        }
        int exc = block_excl_scan_int(runc, tid, s_pi);
#pragma unroll
        for (int j = 0; j < IPT; j++) offs[1 + tid * IPT + j] = exc + c[j];
        __syncthreads();
    }

    // ---- 4. scatter (counting sort); cursors live in ecdf region ------------
    {
        int* cursor = (int*)ecdf;
        for (int b = tid; b < NS; b += NTHREADS) cursor[b] = offs[b];
        __syncthreads();
#pragma unroll
        for (int i = 0; i < IPT; i++) {
            float x = lx[i];
            int b = (int)(x * 8192.0f);
            if (b > NS - 1) b = NS - 1;
            int pos = atomicAdd(&cursor[b], 1);
            xs[pos] = x;
            cw[pos] = lw[i];
        }
        __syncthreads();
    }

    // ---- 5. per-bucket insertion sort (avg occupancy 1) ---------------------
    for (int b = tid; b < NS; b += NTHREADS) {
        int s = offs[b], e = offs[b + 1];
        for (int i = s + 1; i < e; i++) {
            float kx = xs[i], kv = cw[i];
            int j = i - 1;
            while (j >= s && xs[j] > kx) { xs[j+1] = xs[j]; cw[j+1] = cw[j]; j--; }
            xs[j+1] = kx; cw[j+1] = kv;
        }
    }
    __syncthreads();

    // ---- 6. cumsum of sorted weights -> cdf (in place) ----------------------
    {
        float v[IPT]; float runf = 0.f;
#pragma unroll
        for (int j = 0; j < IPT; j++) { runf += cw[tid * IPT + j]; v[j] = runf; }
        float excf = block_excl_scan_float(runf, tid, s_pf);
#pragma unroll
        for (int j = 0; j < IPT; j++) cw[tid * IPT + j] = excf + v[j];
        __syncthreads();
    }

    // ---- 7. rasterize circular CDF: SCATTER over segments -------------------
    // segment i owns grid j with r in (xs[i], xs[i+1]]; half-open ranges
    // [J(xs[i]), J(xs[i+1])) per period = exact deterministic partition.
    // t computed by DIVISION to match reference rounding exactly (matters in
    // wild-extrapolation segments where t is huge).
#pragma unroll
    for (int jj = 0; jj < IPT; jj++) {
        int i = tid + jj * NTHREADS;
        if (i >= NS - 1) continue;             // NS-1 segments
        float x0  = xs[i],  x1v = xs[i + 1];
        float y0  = cw[i],  y1v = cw[i + 1];
        float dx  = x1v - x0;
        float dy  = y1v - y0;
#pragma unroll
        for (int p = 0; p < 3; p++) {
            const int jmin = (p == 0) ? 0 : (p == 1 ? 8192 : 16384);
            const int jmax = (p == 0) ? 8192 : (p == 1 ? 16384 : NG - 1);
            int js = (i == 0)      ? jmin : find_jstart(x0,  p, jmin, jmax);
            int je = (i == NS - 2) ? jmax : find_jstart(x1v, p, jmin, jmax);
            float fi = (float)(p - 1);
            for (int j = js; j < je; j++) {
                float xn = fmaf((float)j, STEPG, -1.0f);
                float r  = xn - fi;
                float t  = (r - x0) / dx;
                ecdf[j]  = fi + fmaf(t, dy, y0);
            }
        }
        if (i == 0) {   // j = NG-1: xnew = 2.0, fi = 2, r = 0 -> segment 0
            float t = (0.0f - x0) / dx;
            ecdf[NG - 1] = 2.0f + fmaf(t, dy, y0);
        }
    }
    __syncthreads();

    // ---- 8. invert CDF: lockstep EXACT bisection (matches jnp.searchsorted
    // probe path bit-for-bit, required because ecdf is non-monotone at period
    // boundaries). Two batches of 8 queries -> 8 independent LDS in flight.
    {
        float alpha = s_alpha;
#pragma unroll
        for (int bb = 0; bb < KPT / QB; bb++) {
            int   lo[QB], hi[QB];
            float yq[QB];
#pragma unroll
            for (int q = 0; q < QB; q++) {
                int k = tid + (bb * QB + q) * NTHREADS;
                yq[q] = (float)k * (1.0f / 8192.0f) - alpha;
                lo[q] = 0; hi[q] = NG;
            }
#pragma unroll
            for (int it = 0; it < 15; it++) {
#pragma unroll
                for (int q = 0; q < QB; q++) {
                    if (lo[q] < hi[q]) {
                        int mid = (lo[q] + hi[q]) >> 1;
                        bool c = ecdf[mid] < yq[q];
                        lo[q] = c ? mid + 1 : lo[q];
                        hi[q] = c ? hi[q] : mid;
                    }
                }
            }
#pragma unroll
            for (int q = 0; q < QB; q++) {
                int k = tid + (bb * QB + q) * NTHREADS;
                float xk = (float)k * (1.0f / 8192.0f);
                int idx = lo[q] - 1;
                idx = idx < 0 ? 0 : (idx > NG - 2 ? NG - 2 : idx);
                float e0 = ecdf[idx], e1 = ecdf[idx + 1];
                float xn0 = fmaf((float)idx,       STEPG, -1.0f);
                float xn1 = fmaf((float)(idx + 1), STEPG, -1.0f);
                float t = (yq[q] - e0) / (e1 - e0);
                hout[k] = fmaf(t, xn1 - xn0, xn0) - xk;
            }
        }
    }
}

// ---------------------------------------------------------------------------
__global__ void __launch_bounds__(NTHREADS)
lcot_dist_kernel()
{
    __shared__ float red[NTHREADS];
    const int row = blockIdx.x, tid = threadIdx.x;
    const float* h1 = g_h + (size_t)row * NS;
    const float* h2 = g_h + (size_t)(LROWS + row) * NS;
    float acc = 0.f;
    for (int i = tid; i < NS; i += NTHREADS) {
        float d = fabsf(h2[i] - h1[i]);
        float m = fminf(d, 1.0f - d);
        acc = fmaf(m, m, acc);
    }
    red[tid] = acc;
    __syncthreads();
    for (int s = NTHREADS / 2; s > 0; s >>= 1) {
        if (tid < s) red[tid] += red[tid + s];
        __syncthreads();
    }
    if (tid == 0) g_rowsum[row] = red[0];
}

__global__ void lcot_finalize_kernel(float* __restrict__ out)
{
    __shared__ float r[LROWS];
    int t = threadIdx.x;
    r[t] = g_rowsum[t];
    __syncthreads();
    for (int s = LROWS / 2; s > 0; s >>= 1) {
        if (t < s) r[t] += r[t + s];
        __syncthreads();
    }
    if (t == 0) out[0] = sqrtf(r[0] / (float)LROWS);
}

extern "C" void kernel_launch(void* const* d_in, const int* in_sizes, int n_in,
                              void* d_out, int out_size)
{
    const float* x1 = (const float*)d_in[0];
    const float* w1 = (const float*)d_in[1];
    const float* x2 = (const float*)d_in[2];
    const float* w2 = (const float*)d_in[3];
    float* out = (float*)d_out;

    size_t dyn = (size_t)(2 * NS) * sizeof(float)
               + (size_t)(NS + 1) * sizeof(int)
               + (size_t)NG * sizeof(float);   // 196612 B

    cudaFuncSetAttribute(lcot_emb_kernel,
                         cudaFuncAttributeMaxDynamicSharedMemorySize, (int)dyn);

    lcot_emb_kernel<<<2 * LROWS, NTHREADS, dyn>>>(x1, w1, x2, w2);
    lcot_dist_kernel<<<LROWS, NTHREADS>>>();
    lcot_finalize_kernel<<<1, LROWS>>>(out);
}

// round 4
// speedup vs baseline: 2.2921x; 2.2921x over previous
#include <cuda_runtime.h>
#include <math.h>

#define LROWS    512
#define NS       8192            // samples per row
#define NREF     8192            // reference grid points
#define NG       (3*NREF)        // 24576 circular-CDF grid points
#define NTHREADS 1024
#define IPT      (NS/NTHREADS)   // 8 items per thread
#define KPT      (NREF/NTHREADS) // 8 inversion queries per thread
#define GPT_P    (NREF/NTHREADS) // 8 grid points per thread per period

#define STEPG     (3.0f/24575.0f)

__device__ float g_rowsum[LROWS];
__device__ float g_h[(size_t)2 * LROWS * NS];   // h1 then h2, 32 MB scratch

// ---------------------------------------------------------------------------
// block-wide exclusive scans (warp shuffle + 32-entry partials)
// ---------------------------------------------------------------------------
__device__ __forceinline__ int block_excl_scan_int(int local_total, int tid, int* s_part)
{
    __syncthreads();
    int lane = tid & 31, wid = tid >> 5;
    int x = local_total;
#pragma unroll
    for (int d = 1; d < 32; d <<= 1) {
        int t = __shfl_up_sync(0xffffffffu, x, d);
        if (lane >= d) x += t;
    }
    if (lane == 31) s_part[wid] = x;
    __syncthreads();
    if (wid == 0) {
        int v = s_part[lane];
        int y = v;
#pragma unroll
        for (int d = 1; d < 32; d <<= 1) {
            int t = __shfl_up_sync(0xffffffffu, y, d);
            if (lane >= d) y += t;
        }
        s_part[lane] = y - v;                  // exclusive warp offsets
    }
    __syncthreads();
    return s_part[wid] + (x - local_total);
}

__device__ __forceinline__ float block_excl_scan_float(float local_total, int tid, float* s_part)
{
    __syncthreads();
    int lane = tid & 31, wid = tid >> 5;
    float x = local_total;
#pragma unroll
    for (int d = 1; d < 32; d <<= 1) {
        float t = __shfl_up_sync(0xffffffffu, x, d);
        if (lane >= d) x += t;
    }
    if (lane == 31) s_part[wid] = x;
    __syncthreads();
    if (wid == 0) {
        float v = s_part[lane];
        float y = v;
#pragma unroll
        for (int d = 1; d < 32; d <<= 1) {
            float t = __shfl_up_sync(0xffffffffu, y, d);
            if (lane >= d) y += t;
        }
        s_part[lane] = y - v;
    }
    __syncthreads();
    return s_part[wid] + (x - local_total);
}

// ---------------------------------------------------------------------------
// one embedding pass per block: grid = 1024 = 2 datasets x 512 rows
// ---------------------------------------------------------------------------
__global__ void __launch_bounds__(NTHREADS, 1)
lcot_emb_kernel(const float* __restrict__ x1, const float* __restrict__ w1,
                const float* __restrict__ x2, const float* __restrict__ w2)
{
    extern __shared__ char smem_raw[];
    float* xs   = (float*)smem_raw;            // [NS]
    float* cw   = xs + NS;                     // [NS]
    int*   offs = (int*)(cw + NS);             // [NS+1]
    float* ecdf = (float*)(offs + (NS + 1));   // [NG]

    __shared__ float s_pf[32];
    __shared__ float s_pf2[32];
    __shared__ int   s_pi[32];
    __shared__ float s_alpha;

    const int tid = threadIdx.x;
    const int bid = blockIdx.x;
    const int row = bid & (LROWS - 1);
    const int ds  = bid >> 9;
    const size_t base = (size_t)row * NS;
    const float* gx = (ds ? x2 : x1) + base;
    const float* gw = (ds ? w2 : w1) + base;
    float* hout = g_h + (size_t)bid * NS;

    // ---- 1. zero histogram --------------------------------------------------
    for (int i = tid; i <= NS; i += NTHREADS) offs[i] = 0;
    __syncthreads();

    // ---- 2. load, histogram, alpha partials ---------------------------------
    float lx[IPT], lw[IPT];
    float pxw = 0.f, pw = 0.f;
#pragma unroll
    for (int i = 0; i < IPT; i++) {
        int idx = tid + i * NTHREADS;
        float x = gx[idx];
        float w = gw[idx];
        lx[i] = x; lw[i] = w;
        pxw += x * w; pw += w;
        int b = (int)(x * 8192.0f);            // exact order-preserving bucket
        if (b > NS - 1) b = NS - 1;
        atomicAdd(&offs[b + 1], 1);
    }
    {
        int lane = tid & 31, wid = tid >> 5;
        float a = pxw, b = pw;
#pragma unroll
        for (int d = 16; d > 0; d >>= 1) {
            a += __shfl_down_sync(0xffffffffu, a, d);
            b += __shfl_down_sync(0xffffffffu, b, d);
        }
        if (lane == 0) { s_pf[wid] = a; s_pf2[wid] = b; }
        __syncthreads();                       // also fences histogram atomics
        if (tid == 0) {
            float sa = 0.f, sb = 0.f;
#pragma unroll
            for (int k = 0; k < 32; k++) { sa += s_pf[k]; sb += s_pf2[k]; }
            s_alpha = sa / sb - 0.5f;
        }
    }

    // ---- 3. exclusive scan of counts -> bucket offsets ----------------------
    {
        int c[IPT]; int runc = 0;
#pragma unroll
        for (int j = 0; j < IPT; j++) {
            runc += offs[1 + tid * IPT + j];
            c[j] = runc;
        }
        int exc = block_excl_scan_int(runc, tid, s_pi);
#pragma unroll
        for (int j = 0; j < IPT; j++) offs[1 + tid * IPT + j] = exc + c[j];
        __syncthreads();
    }

    // ---- 4. scatter (counting sort); cursors live in ecdf region ------------
    {
        int* cursor = (int*)ecdf;
        for (int b = tid; b < NS; b += NTHREADS) cursor[b] = offs[b];
        __syncthreads();
#pragma unroll
        for (int i = 0; i < IPT; i++) {
            float x = lx[i];
            int b = (int)(x * 8192.0f);
            if (b > NS - 1) b = NS - 1;
            int pos = atomicAdd(&cursor[b], 1);
            xs[pos] = x;
            cw[pos] = lw[i];
        }
        __syncthreads();
    }

    // ---- 5. per-bucket insertion sort (avg occupancy 1) ---------------------
    for (int b = tid; b < NS; b += NTHREADS) {
        int s = offs[b], e = offs[b + 1];
        for (int i = s + 1; i < e; i++) {
            float kx = xs[i], kv = cw[i];
            int j = i - 1;
            while (j >= s && xs[j] > kx) { xs[j+1] = xs[j]; cw[j+1] = cw[j]; j--; }
            xs[j+1] = kx; cw[j+1] = kv;
        }
    }
    __syncthreads();

    // ---- 6. cumsum of sorted weights -> cdf (in place) ----------------------
    {
        float v[IPT]; float runf = 0.f;
#pragma unroll
        for (int j = 0; j < IPT; j++) { runf += cw[tid * IPT + j]; v[j] = runf; }
        float excf = block_excl_scan_float(runf, tid, s_pf);
#pragma unroll
        for (int j = 0; j < IPT; j++) cw[tid * IPT + j] = excf + v[j];
        __syncthreads();
    }

    // ---- 7. rasterize circular CDF onto 3N grid (GATHER, per-period) --------
    // lower_bound via the exact bucket map: only bucket b needs a strict-less
    // scan (avg occupancy 1). fi is a per-period constant (except j = NG-1).
#pragma unroll
    for (int p = 0; p < 3; p++) {
        const float fip = (float)(p - 1);
#pragma unroll
        for (int jj = 0; jj < GPT_P; jj++) {
            int j = p * NREF + tid + jj * NTHREADS;
            float xn = fmaf((float)j, STEPG, -1.0f);
            float fi = fip;
            if (j == NG - 1) fi = floorf(xn);   // xn ~ 2.0 exactly
            float r = xn - fi;
            int b = (int)(r * 8192.0f);
            if (b > NS - 1) b = NS - 1;
            if (b < 0) b = 0;
            int lo = offs[b], hi = offs[b + 1];
            int cnt = lo;
            for (int i = lo; i < hi; i++) cnt += (xs[i] < r) ? 1 : 0;
            int idx = cnt - 1;
            idx = idx < 0 ? 0 : (idx > NS - 2 ? NS - 2 : idx);
            float x0 = xs[idx], x1v = xs[idx + 1];
            float y0 = cw[idx], y1 = cw[idx + 1];
            float t = (r - x0) / (x1v - x0);
            ecdf[j] = fi + fmaf(t, y1 - y0, y0);
        }
    }
    __syncthreads();

    // ---- 8. invert CDF: lockstep EXACT bisection (same probe path as
    // jnp.searchsorted; 8 independent LDS in flight per iteration) ------------
    {
        float alpha = s_alpha;
        int   lo[KPT], hi[KPT];
        float yq[KPT];
#pragma unroll
        for (int q = 0; q < KPT; q++) {
            int k = tid + q * NTHREADS;
            yq[q] = (float)k * (1.0f / 8192.0f) - alpha;
            lo[q] = 0; hi[q] = NG;
        }
#pragma unroll
        for (int it = 0; it < 15; it++) {
#pragma unroll
            for (int q = 0; q < KPT; q++) {
                if (lo[q] < hi[q]) {
                    int mid = (lo[q] + hi[q]) >> 1;
                    bool c = ecdf[mid] < yq[q];
                    lo[q] = c ? mid + 1 : lo[q];
                    hi[q] = c ? hi[q] : mid;
                }
            }
        }
#pragma unroll
        for (int q = 0; q < KPT; q++) {
            int k = tid + q * NTHREADS;
            float xk = (float)k * (1.0f / 8192.0f);
            int idx = lo[q] - 1;
            idx = idx < 0 ? 0 : (idx > NG - 2 ? NG - 2 : idx);
            float e0 = ecdf[idx], e1 = ecdf[idx + 1];
            float xn0 = fmaf((float)idx,       STEPG, -1.0f);
            float xn1 = fmaf((float)(idx + 1), STEPG, -1.0f);
            float t = (yq[q] - e0) / (e1 - e0);
            hout[k] = fmaf(t, xn1 - xn0, xn0) - xk;
        }
    }
}

// ---------------------------------------------------------------------------
__global__ void __launch_bounds__(512)
lcot_dist_kernel()
{
    __shared__ float red[512];
    const int row = blockIdx.x, tid = threadIdx.x;
    const float* h1 = g_h + (size_t)row * NS;
    const float* h2 = g_h + (size_t)(LROWS + row) * NS;
    float acc = 0.f;
    for (int i = tid; i < NS; i += 512) {
        float d = fabsf(h2[i] - h1[i]);
        float m = fminf(d, 1.0f - d);
        acc = fmaf(m, m, acc);
    }
    red[tid] = acc;
    __syncthreads();
    for (int s = 256; s > 0; s >>= 1) {
        if (tid < s) red[tid] += red[tid + s];
        __syncthreads();
    }
    if (tid == 0) g_rowsum[row] = red[0];
}

__global__ void lcot_finalize_kernel(float* __restrict__ out)
{
    __shared__ float r[LROWS];
    int t = threadIdx.x;
    r[t] = g_rowsum[t];
    __syncthreads();
    for (int s = LROWS / 2; s > 0; s >>= 1) {
        if (t < s) r[t] += r[t + s];
        __syncthreads();
    }
    if (t == 0) out[0] = sqrtf(r[0] / (float)LROWS);
}

extern "C" void kernel_launch(void* const* d_in, const int* in_sizes, int n_in,
                              void* d_out, int out_size)
{
    const float* x1 = (const float*)d_in[0];
    const float* w1 = (const float*)d_in[1];
    const float* x2 = (const float*)d_in[2];
    const float* w2 = (const float*)d_in[3];
    float* out = (float*)d_out;

    size_t dyn = (size_t)(2 * NS) * sizeof(float)
               + (size_t)(NS + 1) * sizeof(int)
               + (size_t)NG * sizeof(float);   // 196612 B

    cudaFuncSetAttribute(lcot_emb_kernel,
                         cudaFuncAttributeMaxDynamicSharedMemorySize, (int)dyn);

    lcot_emb_kernel<<<2 * LROWS, NTHREADS, dyn>>>(x1, w1, x2, w2);
    lcot_dist_kernel<<<LROWS, 512>>>();
    lcot_finalize_kernel<<<1, LROWS>>>(out);
}